// round 1
// baseline (speedup 1.0000x reference)
#include <cuda_runtime.h>

#define T_STEPS 1000
#define BATCH   4096
#define IN_SZ   8
#define HID     50
#define OUT_SZ  6
#define JTOT    56            // 50 hidden rows + 6 output rows, fused
#define GB      4             // batch elements per block
#define NTHREADS (GB * JTOT)  // 224
#define KP      52            // k padded to multiple of 4
#define RPAD    64            // r row stride in shared (16B aligned, bank spread)
#define DT_F    0.1f

typedef unsigned long long ull;

__device__ __forceinline__ ull pack2(float lo, float hi) {
    ull u; asm("mov.b64 %0, {%1, %2};" : "=l"(u) : "f"(lo), "f"(hi)); return u;
}
__device__ __forceinline__ void unpack2(ull u, float& lo, float& hi) {
    asm("mov.b64 {%0, %1}, %2;" : "=f"(lo), "=f"(hi) : "l"(u));
}
// packed fp32x2 FMA: acc = a * b + acc  (two fp32 lanes per instruction)
#define FMA2(acc, a, b) asm("fma.rn.f32x2 %0, %1, %2, %0;" : "+l"(acc) : "l"(a), "l"(b))

__global__ void __launch_bounds__(NTHREADS, 2) biornn_kernel(
    const float* __restrict__ x,      // (T, B, 8)
    const float* __restrict__ Win,    // (50, 8)
    const float* __restrict__ Wrec,   // (50, 50)
    const float* __restrict__ bias,   // (50,)
    const float* __restrict__ Wow,    // (6, 50)
    const float* __restrict__ Wob,    // (6,)
    float* __restrict__ out)          // (T, B, 6)
{
    __shared__ float r_s[2][GB][RPAD];

    const int tid = threadIdx.x;
    const int bl  = tid / JTOT;          // local batch index 0..GB-1
    const int j   = tid - bl * JTOT;     // fused row index 0..55
    const int b   = blockIdx.x * GB + bl;
    const bool is_h = (j < HID);

    // zero shared (incl. pad columns which stay 0 forever)
    for (int i = tid; i < 2 * GB * RPAD; i += NTHREADS)
        ((float*)r_s)[i] = 0.f;

    // ---- load this thread's weight row into registers, packed as f32x2 pairs ----
    ull w[KP / 2];        // 26 x (2 fp32)
    ull winp[IN_SZ / 2];  // 4  x (2 fp32)
    float bj;
    {
        const float* row = is_h ? (Wrec + j * HID) : (Wow + (j - HID) * HID);
#pragma unroll
        for (int kk = 0; kk < KP / 2; kk++) {
            const int k0 = 2 * kk, k1 = 2 * kk + 1;
            const float a = (k0 < HID) ? row[k0] : 0.f;
            const float c = (k1 < HID) ? row[k1] : 0.f;
            w[kk] = pack2(a, c);
        }
        if (is_h) {
#pragma unroll
            for (int ii = 0; ii < IN_SZ / 2; ii++)
                winp[ii] = pack2(Win[j * IN_SZ + 2 * ii], Win[j * IN_SZ + 2 * ii + 1]);
            bj = bias[j];
        } else {
#pragma unroll
            for (int ii = 0; ii < IN_SZ / 2; ii++) winp[ii] = 0ULL;
            bj = Wob[j - HID];
        }
    }

    float h = 0.f;
    const float* xrow = x + (size_t)b * IN_SZ;   // advance by BATCH*IN_SZ per step

    __syncthreads();

    int buf = 0;
#pragma unroll 1
    for (int t = 0; t < T_STEPS; t++) {
        // publish r = relu(h) for this step (hidden rows only)
        if (is_h) r_s[buf][bl][j] = fmaxf(h, 0.f);

        // broadcast-load x_t[b] (32B, same address for all 56 threads of b)
        const ulonglong2* xp =
            reinterpret_cast<const ulonglong2*>(xrow + (size_t)t * (BATCH * IN_SZ));
        const ulonglong2 x0 = xp[0];   // x[0..3]
        const ulonglong2 x1 = xp[1];   // x[4..7]

        __syncthreads();

        ull acc_a = pack2(bj, 0.f);
        ull acc_b = 0ULL;
        FMA2(acc_a, winp[0], x0.x);
        FMA2(acc_b, winp[1], x0.y);
        FMA2(acc_a, winp[2], x1.x);
        FMA2(acc_b, winp[3], x1.y);

        const ulonglong2* rp =
            reinterpret_cast<const ulonglong2*>(&r_s[buf][bl][0]);
#pragma unroll
        for (int kk = 0; kk < KP / 4; kk++) {     // 13 iterations, LDS.128 each
            const ulonglong2 r2 = rp[kk];
            FMA2(acc_a, w[2 * kk],     r2.x);
            FMA2(acc_b, w[2 * kk + 1], r2.y);
        }

        float a0, a1, b0, b1;
        unpack2(acc_a, a0, a1);
        unpack2(acc_b, b0, b1);
        const float acc = (a0 + a1) + (b0 + b1);

        if (is_h) {
            // h += DT * (acc - h), acc already includes bias + x·Win + r·Wrec
            h = fmaf(DT_F, acc - h, h);
        } else {
            out[((size_t)t * BATCH + b) * OUT_SZ + (j - HID)] = acc;
        }
        buf ^= 1;
    }
}

extern "C" void kernel_launch(void* const* d_in, const int* in_sizes, int n_in,
                              void* d_out, int out_size) {
    const float* x    = (const float*)d_in[0];
    const float* Win  = (const float*)d_in[1];
    const float* Wrec = (const float*)d_in[2];
    const float* bias = (const float*)d_in[3];
    const float* Wow  = (const float*)d_in[4];
    const float* Wob  = (const float*)d_in[5];
    float* out = (float*)d_out;

    biornn_kernel<<<BATCH / GB, NTHREADS>>>(x, Win, Wrec, bias, Wow, Wob, out);
}

// round 2
// speedup vs baseline: 1.1756x; 1.1756x over previous
#include <cuda_runtime.h>

#define T_STEPS 1000
#define BATCH   4096
#define IN_SZ   8
#define HID     50
#define OUT_SZ  6
#define JTOT    56              // 50 hidden rows + 6 output rows, fused
#define KP      56              // k padded: 28 floats per half-thread
#define KHALF   28              // floats per k-half
#define NT      (JTOT * 2)      // 112 threads: (row j, k-half) pairs, 1 batch elem/block
#define RPAD    64              // r row stride in shared
#define DT_F    0.1f

typedef unsigned long long ull;

__device__ __forceinline__ ull pack2(float lo, float hi) {
    ull u; asm("mov.b64 %0, {%1, %2};" : "=l"(u) : "f"(lo), "f"(hi)); return u;
}
__device__ __forceinline__ void unpack2(ull u, float& lo, float& hi) {
    asm("mov.b64 {%0, %1}, %2;" : "=f"(lo), "=f"(hi) : "l"(u));
}
#define FMA2(acc, a, b) asm("fma.rn.f32x2 %0, %1, %2, %0;" : "+l"(acc) : "l"(a), "l"(b))
#define ADD2(d, a, b)   asm("add.rn.f32x2 %0, %1, %2;" : "=l"(d) : "l"(a), "l"(b))

__global__ void __launch_bounds__(NT, 8) biornn_kernel(
    const float* __restrict__ x,      // (T, B, 8)
    const float* __restrict__ Win,    // (50, 8)
    const float* __restrict__ Wrec,   // (50, 50)
    const float* __restrict__ bias,   // (50,)
    const float* __restrict__ Wow,    // (6, 50)
    const float* __restrict__ Wob,    // (6,)
    float* __restrict__ out)          // (T, B, 6)
{
    __shared__ float r_s[2][RPAD];

    const int tid  = threadIdx.x;
    const int half = tid & 1;            // k-half: 0 -> floats [0,28), 1 -> [28,56)
    const int j    = tid >> 1;           // fused row 0..55
    const int b    = blockIdx.x;
    const bool is_h  = (j < HID);
    const bool owner = (half == 0);

    // zero shared (pad columns stay 0 forever)
    for (int i = tid; i < 2 * RPAD; i += NT) ((float*)r_s)[i] = 0.f;

    // ---- weights for this (row, k-half) into registers as f32x2 pairs ----
    ull w[KHALF / 2];   // 14 pairs
    ull winp[2];        // this half's 4 input weights
    float bj;
    {
        const float* row = is_h ? (Wrec + j * HID) : (Wow + (j - HID) * HID);
        const int kbase = half * KHALF;
#pragma unroll
        for (int i = 0; i < KHALF / 2; i++) {
            const int k0 = kbase + 2 * i, k1 = k0 + 1;
            const float a = (k0 < HID) ? row[k0] : 0.f;
            const float c = (k1 < HID) ? row[k1] : 0.f;
            w[i] = pack2(a, c);
        }
        if (is_h) {
            const float* wi = Win + j * IN_SZ + half * 4;
            winp[0] = pack2(wi[0], wi[1]);
            winp[1] = pack2(wi[2], wi[3]);
            bj = owner ? bias[j] : 0.f;
        } else {
            winp[0] = 0ULL; winp[1] = 0ULL;
            bj = owner ? Wob[j - HID] : 0.f;
        }
    }

    float h = 0.f;
    // each thread fetches the 16B of x it consumes: x[t][b][half*4 .. half*4+3]
    const ulonglong2* xp = reinterpret_cast<const ulonglong2*>(
        x + (size_t)b * IN_SZ + half * 4);
    const size_t xstride = (size_t)BATCH * IN_SZ / 4;   // in ulonglong2 units: 8192
    float* outp = out + (size_t)b * OUT_SZ + (j - HID); // valid only for out rows

    ulonglong2 xc = *xp;                 // prefetch x_0
    xp += xstride;

    __syncthreads();

    int buf = 0;
#pragma unroll 1
    for (int t = 0; t < T_STEPS; t++) {
        // publish r = relu(h) for this step (hidden-row owners only)
        if (owner && is_h) r_s[buf][j] = fmaxf(h, 0.f);

        // prefetch x_{t+1} (clamped on last iter) — latency hidden by barrier+compute
        const ulonglong2* npx = (t < T_STEPS - 1) ? xp : (xp - xstride);
        const ulonglong2 xn = *npx;
        xp += xstride;

        __syncthreads();

        ull acc_a = pack2(bj, 0.f);
        ull acc_b = 0ULL;
        FMA2(acc_a, winp[0], xc.x);
        FMA2(acc_b, winp[1], xc.y);

        const ulonglong2* rp =
            reinterpret_cast<const ulonglong2*>(&r_s[buf][0]) + half * (KHALF / 4);
#pragma unroll
        for (int kk = 0; kk < KHALF / 4; kk++) {   // 7 x LDS.128
            const ulonglong2 r2 = rp[kk];
            FMA2(acc_a, w[2 * kk],     r2.x);
            FMA2(acc_b, w[2 * kk + 1], r2.y);
        }

        ull accs; ADD2(accs, acc_a, acc_b);
        float s0, s1; unpack2(accs, s0, s1);
        float s = s0 + s1;
        s += __shfl_xor_sync(0xffffffffu, s, 1);   // combine k-halves

        if (owner) {
            if (is_h) {
                h = fmaf(DT_F, s - h, h);          // h += DT*(acc - h)
            } else {
                outp[(size_t)t * (BATCH * OUT_SZ)] = s;
            }
        }
        xc = xn;
        buf ^= 1;
    }
}

extern "C" void kernel_launch(void* const* d_in, const int* in_sizes, int n_in,
                              void* d_out, int out_size) {
    const float* x    = (const float*)d_in[0];
    const float* Win  = (const float*)d_in[1];
    const float* Wrec = (const float*)d_in[2];
    const float* bias = (const float*)d_in[3];
    const float* Wow  = (const float*)d_in[4];
    const float* Wob  = (const float*)d_in[5];
    float* out = (float*)d_out;

    biornn_kernel<<<BATCH, NT>>>(x, Win, Wrec, bias, Wow, Wob, out);
}